// round 6
// baseline (speedup 1.0000x reference)
#include <cuda_runtime.h>
#include <cstdint>

// QConv2d binarized conv: x(32,64,128,128) f32, w(64,64,3,3) OIHW,
// stride=2, pad=1 -> out(32,64,64,64) f32.
// sign-binarize both; conv == (576 - corr) - 2*popcount(xor).

#define NB 32
#define CIN 64
#define H 128
#define W 128
#define OC 64
#define OH 64
#define OW 64

// Scratch (device globals: allocation-free per harness rules)
__device__ unsigned int       g_xlo[NB * H * W];     // 2 MB (c0-31 plane)
__device__ unsigned int       g_xhi[NB * H * W];     // 2 MB (c32-63 plane)
__device__ unsigned long long g_wpack[OC * 10];      // 9 taps + pad per o (80B stride)
__device__ float              g_corr2[4 * OC];       // 576 - border correction

// ---------------------------------------------------------------------------
// Pack x (stable across R3/R4: ~24us, ~70% DRAM)
// ---------------------------------------------------------------------------
__global__ void __launch_bounds__(256) pack_x_kernel(const float* __restrict__ x) {
    int g = blockIdx.x * blockDim.x + threadIdx.x;   // 0 .. 262143
    int half = g & 1;
    int w4   = ((g >> 1) & 31) * 4;
    int h    = (g >> 6) & 127;
    int n    = g >> 13;

    const float* base = x + ((long)(n * CIN + half * 32) * H + h) * W + w4;

    unsigned int b0 = 0, b1 = 0, b2 = 0, b3 = 0;
#pragma unroll 16
    for (int c = 0; c < 32; c++) {
        float4 v = *reinterpret_cast<const float4*>(base + (long)c * (H * W));
        b0 |= (unsigned int)(v.x >= 0.0f) << c;
        b1 |= (unsigned int)(v.y >= 0.0f) << c;
        b2 |= (unsigned int)(v.z >= 0.0f) << c;
        b3 |= (unsigned int)(v.w >= 0.0f) << c;
    }
    unsigned int* plane = half ? g_xhi : g_xlo;
    uint4 val; val.x = b0; val.y = b1; val.z = b2; val.w = b3;
    *reinterpret_cast<uint4*>(plane + ((long)(n * H + h) * W + w4)) = val;
}

// ---------------------------------------------------------------------------
// Pack w: one block per o; ballot packs sign bits; builds (576-corr) table.
// ---------------------------------------------------------------------------
__global__ void __launch_bounds__(64) pack_w_kernel(const float* __restrict__ w) {
    __shared__ unsigned int s_lo[9], s_hi[9];
    __shared__ int s_pc[9];
    int o = blockIdx.x;
    int i = threadIdx.x;
    int warp = i >> 5;
    int lane = i & 31;

    const float* wr = w + (o * CIN + i) * 9;
    float v[9];
#pragma unroll
    for (int t = 0; t < 9; t++) v[t] = wr[t];

#pragma unroll
    for (int t = 0; t < 9; t++) {
        unsigned int m = __ballot_sync(0xFFFFFFFFu, v[t] >= 0.0f);
        if (lane == 0) {
            if (warp == 0) s_lo[t] = m; else s_hi[t] = m;
        }
    }
    __syncthreads();
    if (i < 9) {
        unsigned long long bits =
            (unsigned long long)s_lo[i] | ((unsigned long long)s_hi[i] << 32);
        g_wpack[o * 10 + i] = bits;
        s_pc[i] = __popcll(bits);
    }
    if (i == 9) g_wpack[o * 10 + 9] = 0ull;
    __syncthreads();
    if (i == 0) {
        float term0 = (float)(64 - 2 * s_pc[0]);
        float c1 = term0 + (float)(64 - 2 * s_pc[1]) + (float)(64 - 2 * s_pc[2]);
        float c2 = term0 + (float)(64 - 2 * s_pc[3]) + (float)(64 - 2 * s_pc[6]);
        float c3 = c1 + c2 - term0;
        g_corr2[0 * OC + o] = 576.0f;
        g_corr2[1 * OC + o] = 576.0f - c1;
        g_corr2[2 * OC + o] = 576.0f - c2;
        g_corr2[3 * OC + o] = 576.0f - c3;
    }
}

// ---------------------------------------------------------------------------
// Conv v3: ILP-4. Each thread computes a 2x2 output patch:
//   oh in {2*bx, 2*bx+1}  x  ow in {lane, lane+32}
// over 32 output channels (warp 0: o 0-31, warp 1: o 32-63).
// oh pair shares the middle input row -> 5 rows x 6 cols x 2 planes
// = 60 tap words in registers. 4 independent popc-accumulate chains hide
// the 4-cyc alu latency; LDS weight broadcast amortized over 4 outputs.
// Block = 64 threads; grid (32, 32) = 1024 CTAs = 2048 warps.
// ---------------------------------------------------------------------------
__global__ void __launch_bounds__(64) conv_kernel(float* __restrict__ out) {
    __shared__ unsigned long long ws[OC * 10];
    __shared__ float scorr[4 * OC];

    int tid = threadIdx.x;
    for (int i = tid; i < OC * 10; i += 64) ws[i] = g_wpack[i];
    for (int i = tid; i < 4 * OC; i += 64) scorr[i] = g_corr2[i];
    __syncthreads();

    int lane  = tid & 31;
    int obase = (tid >> 5) * 32;       // warp -> o-half
    int bx    = blockIdx.x;            // oh pair: oh0 = 2*bx, oh1 = 2*bx+1
    int n     = blockIdx.y;
    int oh0   = 2 * bx;

    const unsigned int* xl = g_xlo + (long)n * (H * W);
    const unsigned int* xh = g_xhi + (long)n * (H * W);

    int ihtop = 4 * bx - 1;            // rows j=0..4 -> ih = ihtop + j
    int c0    = 2 * lane - 1;          // first tap col for ow = lane

    // taps[j][k]: k=0..2 -> ow=lane cols (c0+kw); k=3..5 -> ow=lane+32 (c0+64+kw)
    unsigned int tlo[5][6], thi[5][6];
#pragma unroll
    for (int j = 0; j < 5; j++) {
        int ih = ihtop + j;
        bool vr = (ih >= 0);           // only j==0 at bx==0 can be invalid
        const unsigned int* rl = xl + ih * W;
        const unsigned int* rh = xh + ih * W;
#pragma unroll
        for (int kw = 0; kw < 3; kw++) {
            bool v = vr && (c0 + kw >= 0);       // lane==0 && kw==0 -> pad
            tlo[j][kw] = v ? rl[c0 + kw] : 0u;
            thi[j][kw] = v ? rh[c0 + kw] : 0u;
            tlo[j][3 + kw] = vr ? rl[c0 + 64 + kw] : 0u;
            thi[j][3 + kw] = vr ? rh[c0 + 64 + kw] : 0u;
        }
    }

    // border-correction classes for the 4 outputs
    int m00 = ((oh0 == 0) ? 1 : 0) | ((lane == 0) ? 2 : 0);  // (oh0, lane)
    int m01 = (oh0 == 0) ? 1 : 0;                            // (oh0, lane+32)
    int m10 = (lane == 0) ? 2 : 0;                           // (oh1, lane)
    const float* cp00 = scorr + m00 * OC + obase;
    const float* cp01 = scorr + m01 * OC + obase;
    const float* cp10 = scorr + m10 * OC + obase;
    const float* cp11 = scorr + 0   * OC + obase;

    float* op = out + ((long)(n * OC + obase) * OH + oh0) * OW;

#pragma unroll 2
    for (int oo = 0; oo < 32; oo++) {
        const unsigned long long* wrow = ws + (obase + oo) * 10;
        const ulonglong2* wp = reinterpret_cast<const ulonglong2*>(wrow);
        ulonglong2 q0 = wp[0], q1 = wp[1], q2 = wp[2], q3 = wp[3];
        unsigned long long q4 = wrow[8];
        unsigned long long wt[9] = {q0.x, q0.y, q1.x, q1.y, q2.x, q2.y, q3.x, q3.y, q4};

        int c00 = 0, c01 = 0, c10 = 0, c11 = 0;
#pragma unroll
        for (int t = 0; t < 9; t++) {
            int kh = t / 3, kw = t % 3;
            unsigned int wl = (unsigned int)wt[t];
            unsigned int wh = (unsigned int)(wt[t] >> 32);
            c00 += __popc(tlo[kh][kw] ^ wl)     + __popc(thi[kh][kw] ^ wh);
            c01 += __popc(tlo[kh][3+kw] ^ wl)   + __popc(thi[kh][3+kw] ^ wh);
            c10 += __popc(tlo[kh+2][kw] ^ wl)   + __popc(thi[kh+2][kw] ^ wh);
            c11 += __popc(tlo[kh+2][3+kw] ^ wl) + __popc(thi[kh+2][3+kw] ^ wh);
        }
        float* po = op + (long)oo * (OH * OW);
        po[lane]           = fmaf(-2.0f, (float)c00, cp00[oo]);
        po[lane + 32]      = fmaf(-2.0f, (float)c01, cp01[oo]);
        po[OW + lane]      = fmaf(-2.0f, (float)c10, cp10[oo]);
        po[OW + lane + 32] = fmaf(-2.0f, (float)c11, cp11[oo]);
    }
}

// ---------------------------------------------------------------------------
extern "C" void kernel_launch(void* const* d_in, const int* in_sizes, int n_in,
                              void* d_out, int out_size) {
    const float* x = (const float*)d_in[0];
    const float* w = (const float*)d_in[1];
    float* out = (float*)d_out;

    pack_x_kernel<<<1024, 256>>>(x);
    pack_w_kernel<<<64, 64>>>(w);
    conv_kernel<<<dim3(32, 32), 64>>>(out);
}

// round 7
// speedup vs baseline: 1.1287x; 1.1287x over previous
#include <cuda_runtime.h>
#include <cstdint>

// QConv2d binarized conv: x(32,64,128,128) f32, w(64,64,3,3) OIHW,
// stride=2, pad=1 -> out(32,64,64,64) f32.
// sign-binarize both; conv == (576 - corr) - 2*popcount(xor).
// R7: conv = R4 topology (128thr CTAs, 4096 warps, ILP-2) + CSA popcount
//     compression (18 POPC -> 5 POPC per output, work shifted to LOP3).

#define NB 32
#define CIN 64
#define H 128
#define W 128
#define OC 64
#define OH 64
#define OW 64

// Scratch (device globals: allocation-free per harness rules)
__device__ unsigned int       g_xlo[NB * H * W];     // 2 MB (c0-31 plane)
__device__ unsigned int       g_xhi[NB * H * W];     // 2 MB (c32-63 plane)
__device__ unsigned long long g_wpack[OC * 10];      // 9 taps + pad per o (80B stride)
__device__ float              g_corr2[4 * OC];       // 576 - border correction

// ---------------------------------------------------------------------------
// Pack x (unchanged control: ~24us, ~70% DRAM)
// ---------------------------------------------------------------------------
__global__ void __launch_bounds__(256) pack_x_kernel(const float* __restrict__ x) {
    int g = blockIdx.x * blockDim.x + threadIdx.x;   // 0 .. 262143
    int half = g & 1;
    int w4   = ((g >> 1) & 31) * 4;
    int h    = (g >> 6) & 127;
    int n    = g >> 13;

    const float* base = x + ((long)(n * CIN + half * 32) * H + h) * W + w4;

    unsigned int b0 = 0, b1 = 0, b2 = 0, b3 = 0;
#pragma unroll 16
    for (int c = 0; c < 32; c++) {
        float4 v = *reinterpret_cast<const float4*>(base + (long)c * (H * W));
        b0 |= (unsigned int)(v.x >= 0.0f) << c;
        b1 |= (unsigned int)(v.y >= 0.0f) << c;
        b2 |= (unsigned int)(v.z >= 0.0f) << c;
        b3 |= (unsigned int)(v.w >= 0.0f) << c;
    }
    unsigned int* plane = half ? g_xhi : g_xlo;
    uint4 val; val.x = b0; val.y = b1; val.z = b2; val.w = b3;
    *reinterpret_cast<uint4*>(plane + ((long)(n * H + h) * W + w4)) = val;
}

// ---------------------------------------------------------------------------
// Pack w (unchanged)
// ---------------------------------------------------------------------------
__global__ void __launch_bounds__(64) pack_w_kernel(const float* __restrict__ w) {
    __shared__ unsigned int s_lo[9], s_hi[9];
    __shared__ int s_pc[9];
    int o = blockIdx.x;
    int i = threadIdx.x;
    int warp = i >> 5;
    int lane = i & 31;

    const float* wr = w + (o * CIN + i) * 9;
    float v[9];
#pragma unroll
    for (int t = 0; t < 9; t++) v[t] = wr[t];

#pragma unroll
    for (int t = 0; t < 9; t++) {
        unsigned int m = __ballot_sync(0xFFFFFFFFu, v[t] >= 0.0f);
        if (lane == 0) {
            if (warp == 0) s_lo[t] = m; else s_hi[t] = m;
        }
    }
    __syncthreads();
    if (i < 9) {
        unsigned long long bits =
            (unsigned long long)s_lo[i] | ((unsigned long long)s_hi[i] << 32);
        g_wpack[o * 10 + i] = bits;
        s_pc[i] = __popcll(bits);
    }
    if (i == 9) g_wpack[o * 10 + 9] = 0ull;
    __syncthreads();
    if (i == 0) {
        float term0 = (float)(64 - 2 * s_pc[0]);
        float c1 = term0 + (float)(64 - 2 * s_pc[1]) + (float)(64 - 2 * s_pc[2]);
        float c2 = term0 + (float)(64 - 2 * s_pc[3]) + (float)(64 - 2 * s_pc[6]);
        float c3 = c1 + c2 - term0;
        g_corr2[0 * OC + o] = 576.0f;
        g_corr2[1 * OC + o] = 576.0f - c1;
        g_corr2[2 * OC + o] = 576.0f - c2;
        g_corr2[3 * OC + o] = 576.0f - c3;
    }
}

// ---------------------------------------------------------------------------
// CSA (3:2 compressor): one LOP3 for sum (a^b^c), one for carry (maj).
// ---------------------------------------------------------------------------
#define CSA(s, c, a, b, x) do {                      \
    unsigned int _u = (a) ^ (b);                     \
    (s) = _u ^ (x);                                  \
    (c) = ((a) & (b)) | (_u & (x));                  \
} while (0)

// Sum of popcounts of 18 words via carry-save tree: 32 LOP3 + 5 POPC.
__device__ __forceinline__ int popcount18(const unsigned int* v) {
    unsigned int s0, s1, s2, s3, s4, s5;
    unsigned int c0, c1, c2, c3, c4, c5, c6, c7, c8;
    CSA(s0, c0, v[0],  v[1],  v[2]);
    CSA(s1, c1, v[3],  v[4],  v[5]);
    CSA(s2, c2, v[6],  v[7],  v[8]);
    CSA(s3, c3, v[9],  v[10], v[11]);
    CSA(s4, c4, v[12], v[13], v[14]);
    CSA(s5, c5, v[15], v[16], v[17]);
    unsigned int t0, t1;
    CSA(t0, c6, s0, s1, s2);
    CSA(t1, c7, s3, s4, s5);
    unsigned int u1 = t0 ^ t1;            // weight-1 plane
    c8 = t0 & t1;
    unsigned int w0, w1, w2, d0, d1, d2, u2, d3;
    CSA(w0, d0, c0, c1, c2);
    CSA(w1, d1, c3, c4, c5);
    CSA(w2, d2, c6, c7, c8);
    CSA(u2, d3, w0, w1, w2);              // weight-2 plane
    unsigned int e0, f0;
    CSA(e0, f0, d0, d1, d2);
    unsigned int u4  = e0 ^ d3;           // weight-4 plane
    unsigned int f1  = e0 & d3;
    unsigned int u8  = f0 ^ f1;           // weight-8 plane
    unsigned int u16 = f0 & f1;           // weight-16 plane
    return __popc(u1) + 2 * __popc(u2) + 4 * __popc(u4)
         + 8 * __popc(u8) + 16 * __popc(u16);
}

// ---------------------------------------------------------------------------
// Conv: R4 topology. Block = 128 threads = 4 warps (2 oh rows x 2 o-halves);
// each thread computes 2 outputs (ow=lane, ow=lane+32) over 32 channels.
// Grid (32, 32) = 1024 CTAs -> 4096 warps. CSA popcount inner loop.
// ---------------------------------------------------------------------------
__global__ void __launch_bounds__(128) conv_kernel(float* __restrict__ out) {
    __shared__ unsigned long long ws[OC * 10];
    __shared__ float scorr[4 * OC];

    int tid = threadIdx.x;
    for (int i = tid; i < OC * 10; i += 128) ws[i] = g_wpack[i];
    for (int i = tid; i < 4 * OC; i += 128) scorr[i] = g_corr2[i];
    __syncthreads();

    int lane  = tid & 31;
    int warp  = tid >> 5;
    int r     = warp & 1;            // oh row within CTA
    int obase = (warp >> 1) * 32;    // o-half
    int oh    = blockIdx.x * 2 + r;
    int n     = blockIdx.y;

    const unsigned int* xl = g_xlo + (long)n * (H * W);
    const unsigned int* xh = g_xhi + (long)n * (H * W);

    int ih0  = 2 * oh - 1;
    int iwa0 = 2 * lane - 1;            // output a: ow = lane
    int iwb0 = 2 * (lane + 32) - 1;     // output b: ow = lane+32 (>= 63, never OOB)

    unsigned int alo[9], ahi[9], blo[9], bhi[9];
#pragma unroll
    for (int kh = 0; kh < 3; kh++) {
#pragma unroll
        for (int kw = 0; kw < 3; kw++) {
            int t  = kh * 3 + kw;
            int ih = ih0 + kh;
            bool vr = (ih >= 0);
            int iwa = iwa0 + kw;
            bool va = vr && (iwa >= 0);
            int ia  = ih * W + iwa;
            alo[t] = va ? xl[ia] : 0u;
            ahi[t] = va ? xh[ia] : 0u;
            int ib  = ih * W + iwb0 + kw;
            blo[t] = vr ? xl[ib] : 0u;
            bhi[t] = vr ? xh[ib] : 0u;
        }
    }

    int mta = ((oh == 0) ? 1 : 0) | ((lane == 0) ? 2 : 0);
    int mtb = (oh == 0) ? 1 : 0;
    const float* cpa = scorr + mta * OC + obase;
    const float* cpb = scorr + mtb * OC + obase;
    float* op = out + (((long)(n * OC + obase)) * OH + oh) * OW;

#pragma unroll 2
    for (int oo = 0; oo < 32; oo++) {
        const unsigned long long* wrow = ws + (obase + oo) * 10;
        const ulonglong2* wp = reinterpret_cast<const ulonglong2*>(wrow);
        ulonglong2 q0 = wp[0], q1 = wp[1], q2 = wp[2], q3 = wp[3];
        unsigned long long q4 = wrow[8];
        unsigned long long wt[9] = {q0.x, q0.y, q1.x, q1.y, q2.x, q2.y, q3.x, q3.y, q4};

        unsigned int va[18], vb[18];
#pragma unroll
        for (int t = 0; t < 9; t++) {
            unsigned int wl = (unsigned int)wt[t];
            unsigned int wh = (unsigned int)(wt[t] >> 32);
            va[2 * t]     = alo[t] ^ wl;
            va[2 * t + 1] = ahi[t] ^ wh;
            vb[2 * t]     = blo[t] ^ wl;
            vb[2 * t + 1] = bhi[t] ^ wh;
        }
        int ca = popcount18(va);
        int cb = popcount18(vb);

        float* po = op + (long)oo * (OH * OW);
        po[lane]      = fmaf(-2.0f, (float)ca, cpa[oo]);
        po[lane + 32] = fmaf(-2.0f, (float)cb, cpb[oo]);
    }
}

// ---------------------------------------------------------------------------
extern "C" void kernel_launch(void* const* d_in, const int* in_sizes, int n_in,
                              void* d_out, int out_size) {
    const float* x = (const float*)d_in[0];
    const float* w = (const float*)d_in[1];
    float* out = (float*)d_out;

    pack_x_kernel<<<1024, 256>>>(x);
    pack_w_kernel<<<64, 64>>>(w);
    conv_kernel<<<dim3(32, 32), 128>>>(out);
}

// round 9
// speedup vs baseline: 1.1623x; 1.0298x over previous
#include <cuda_runtime.h>
#include <cstdint>

// QConv2d binarized conv via legacy mma.sync IMMA (s8, m16n8k32).
// x(32,64,128,128) f32, w(64,64,3,3) OIHW, stride=2, pad=1 -> out(32,64,64,64) f32.
// Phase 1: bit-pack signs. Phase 2: per warp, M-tile = 16 ow x N=64 oc,
// K = 576 (9 taps x 64 ic) as 18 k32 MMA steps. +-1 as s8; pad rows = 0 s8
// -> contribute exactly 0 (no border correction).

#define NB 32
#define CIN 64
#define H 128
#define W 128
#define OC 64
#define OH 64
#define OW 64

__device__ unsigned int g_xlo[NB * H * W];   // 2 MB: channels 0-31 sign bits
__device__ unsigned int g_xhi[NB * H * W];   // 2 MB: channels 32-63 sign bits
// B fragments, coalesced per (tap, j-tile): [(tap*8 + j)*32 + lane] -> uint4
// (b0_k0, b1_k0, b0_k1, b1_k1) for n-cols 8j..8j+7.
__device__ uint4 g_wfrag[9 * 8 * 32];

// ---------------------------------------------------------------------------
// nibble (4 sign bits) -> 4 packed s8: bit=1 -> +1 (0x01), bit=0 -> -1 (0xFF)
// ---------------------------------------------------------------------------
__device__ __forceinline__ unsigned int expand4(unsigned int nib) {
    unsigned int s = (nib | (nib << 7) | (nib << 14) | (nib << 21)) & 0x01010101u;
    return (s * 0xFEu) ^ 0xFFFFFFFFu;
}

__device__ __forceinline__ void mma_s8(int* c,
    unsigned int a0, unsigned int a1, unsigned int a2, unsigned int a3,
    unsigned int b0, unsigned int b1) {
    asm volatile(
        "mma.sync.aligned.m16n8k32.row.col.s32.s8.s8.s32 "
        "{%0,%1,%2,%3}, {%4,%5,%6,%7}, {%8,%9}, {%0,%1,%2,%3};"
        : "+r"(c[0]), "+r"(c[1]), "+r"(c[2]), "+r"(c[3])
        : "r"(a0), "r"(a1), "r"(a2), "r"(a3), "r"(b0), "r"(b1));
}

// ---------------------------------------------------------------------------
// Pack x (proven: ~24us, ~70% DRAM)
// ---------------------------------------------------------------------------
__global__ void __launch_bounds__(256) pack_x_kernel(const float* __restrict__ x) {
    int g = blockIdx.x * blockDim.x + threadIdx.x;
    int half = g & 1;
    int w4   = ((g >> 1) & 31) * 4;
    int h    = (g >> 6) & 127;
    int n    = g >> 13;

    const float* base = x + ((long)(n * CIN + half * 32) * H + h) * W + w4;

    unsigned int b0 = 0, b1 = 0, b2 = 0, b3 = 0;
#pragma unroll 16
    for (int c = 0; c < 32; c++) {
        float4 v = *reinterpret_cast<const float4*>(base + (long)c * (H * W));
        b0 |= (unsigned int)(v.x >= 0.0f) << c;
        b1 |= (unsigned int)(v.y >= 0.0f) << c;
        b2 |= (unsigned int)(v.z >= 0.0f) << c;
        b3 |= (unsigned int)(v.w >= 0.0f) << c;
    }
    unsigned int* plane = half ? g_xhi : g_xlo;
    uint4 val; val.x = b0; val.y = b1; val.z = b2; val.w = b3;
    *reinterpret_cast<uint4*>(plane + ((long)(n * H + h) * W + w4)) = val;
}

// ---------------------------------------------------------------------------
// Pack w: one CTA. Phase 1: 576 threads pack sign bits per (o, tap).
// Phase 2: 288 threads (9 taps x 32 lanes) emit mma B-fragments.
// B frag layout (m16n8k32.col): b0 = col(o)=8j+(lane>>2), k=4*(lane&3)+[0,3];
// b1 = k+16; k-step 1 adds +32 (hi half of the 64-bit channel word).
// ---------------------------------------------------------------------------
__global__ void __launch_bounds__(576) pack_w_kernel(const float* __restrict__ w) {
    __shared__ unsigned long long s_w[OC * 9];
    int t = threadIdx.x;
    {
        int o = t / 9, tap = t % 9;
        unsigned long long bits = 0;
#pragma unroll 8
        for (int c = 0; c < CIN; c++) {
            float v = w[(o * CIN + c) * 9 + tap];
            bits |= (unsigned long long)(v >= 0.0f) << c;
        }
        s_w[o * 9 + tap] = bits;
    }
    __syncthreads();
    if (t < 288) {
        int lane = t & 31;
        int tap  = t >> 5;
        int gq   = lane >> 2;      // n-col group
        int qc   = lane & 3;
#pragma unroll
        for (int j = 0; j < 8; j++) {
            int o = 8 * j + gq;
            unsigned long long wb = s_w[o * 9 + tap];
            uint4 f;
            f.x = expand4((unsigned int)(wb >> (4 * qc))        & 0xFu);  // k0, b0
            f.y = expand4((unsigned int)(wb >> (16 + 4 * qc))   & 0xFu);  // k0, b1
            f.z = expand4((unsigned int)(wb >> (32 + 4 * qc))   & 0xFu);  // k1, b0
            f.w = expand4((unsigned int)(wb >> (48 + 4 * qc))   & 0xFu);  // k1, b1
            g_wfrag[(tap * 8 + j) * 32 + lane] = f;
        }
    }
}

// ---------------------------------------------------------------------------
// Conv: warp = one M-tile (16 consecutive ow at one (n, oh)) x N=64.
// 8192 warps = 1024 CTAs x 256 thr. Accumulators: 8 n-tiles x 4 s32.
// A fragments expanded from bit planes in registers; pad -> s8 zeros.
// ---------------------------------------------------------------------------
__global__ void __launch_bounds__(256) conv_mma_kernel(float* __restrict__ out) {
    int gw   = (blockIdx.x * 256 + threadIdx.x) >> 5;   // 0..8191
    int lane = threadIdx.x & 31;
    int ow0  = (gw & 3) * 16;
    int oh   = (gw >> 2) & 63;
    int n    = gw >> 8;
    int qr   = lane >> 2;      // row in group (0..7)
    int qc   = lane & 3;
    int ow_a = ow0 + qr;
    int ow_b = ow_a + 8;

    const unsigned int* xl = g_xlo + (long)n * (H * W);
    const unsigned int* xh = g_xhi + (long)n * (H * W);

    int acc[32];
#pragma unroll
    for (int i = 0; i < 32; i++) acc[i] = 0;

    int sh0 = 4 * qc;
    int sh1 = 16 + 4 * qc;

#pragma unroll
    for (int kh = 0; kh < 3; kh++) {
        int ih = 2 * oh - 1 + kh;
        bool vr = (ih >= 0);                 // ih <= 127 always
#pragma unroll
        for (int kw = 0; kw < 3; kw++) {
            int tap = kh * 3 + kw;
            int iwa = 2 * ow_a - 1 + kw;     // [-1, 127]
            int iwb = iwa + 16;              // always >= 15
            bool pa = vr && (iwa >= 0);
            bool pb = vr;

            unsigned int loa = pa ? xl[ih * W + iwa] : 0u;
            unsigned int hia = pa ? xh[ih * W + iwa] : 0u;
            unsigned int lob = pb ? xl[ih * W + iwb] : 0u;
            unsigned int hib = pb ? xh[ih * W + iwb] : 0u;

            // A fragments (pad rows -> s8 0x00 so they contribute 0)
            unsigned int a0 = pa ? expand4((loa >> sh0) & 0xFu) : 0u;  // row a, k0
            unsigned int a1 = pb ? expand4((lob >> sh0) & 0xFu) : 0u;  // row b, k0
            unsigned int a2 = pa ? expand4((loa >> sh1) & 0xFu) : 0u;  // row a, k0+16
            unsigned int a3 = pb ? expand4((lob >> sh1) & 0xFu) : 0u;  // row b, k0+16
            unsigned int a4 = pa ? expand4((hia >> sh0) & 0xFu) : 0u;  // row a, k1
            unsigned int a5 = pb ? expand4((hib >> sh0) & 0xFu) : 0u;
            unsigned int a6 = pa ? expand4((hia >> sh1) & 0xFu) : 0u;
            unsigned int a7 = pb ? expand4((hib >> sh1) & 0xFu) : 0u;

            const uint4* wf = g_wfrag + tap * 8 * 32 + lane;
#pragma unroll
            for (int j = 0; j < 8; j++) {
                uint4 b = wf[j * 32];
                mma_s8(acc + 4 * j, a0, a1, a2, a3, b.x, b.y);  // channels 0-31
                mma_s8(acc + 4 * j, a4, a5, a6, a7, b.z, b.w);  // channels 32-63
            }
        }
    }

    // Epilogue: c0=(row a, o=8j+2qc), c1=(row a, o+1), c2=(row b, o), c3=(row b, o+1)
    float* ob = out + ((long)(n * OC) * OH + oh) * OW;
#pragma unroll
    for (int j = 0; j < 8; j++) {
        int o0 = 8 * j + 2 * qc;
        float* p0 = ob + (long)o0 * (OH * OW);
        float* p1 = p0 + (OH * OW);
        p0[ow_a] = (float)acc[4 * j + 0];
        p1[ow_a] = (float)acc[4 * j + 1];
        p0[ow_b] = (float)acc[4 * j + 2];
        p1[ow_b] = (float)acc[4 * j + 3];
    }
}

// ---------------------------------------------------------------------------
// 4 launches: conv sits at stream index 2 (mod 4) so ncu's skip-6 capture
// lands on conv. Trailing pack_w repeat is idempotent (same inputs).
// ---------------------------------------------------------------------------
extern "C" void kernel_launch(void* const* d_in, const int* in_sizes, int n_in,
                              void* d_out, int out_size) {
    const float* x = (const float*)d_in[0];
    const float* w = (const float*)d_in[1];
    float* out = (float*)d_out;

    pack_x_kernel<<<1024, 256>>>(x);
    pack_w_kernel<<<1, 576>>>(w);
    conv_mma_kernel<<<1024, 256>>>(out);
    pack_w_kernel<<<1, 576>>>(w);
}

// round 10
// speedup vs baseline: 1.4115x; 1.2144x over previous
#include <cuda_runtime.h>
#include <cstdint>

// QConv2d binarized conv via mma.sync IMMA (s8, m16n8k32).
// x(32,64,128,128) f32, w(64,64,3,3) OIHW, stride=2, pad=1 -> out(32,64,64,64) f32.
// R10: single parallel pack_w (64 CTAs, ballot + fused fragment emission),
//      duplicate launch removed. Conv unchanged from R9 (verified, ~22us).

#define NB 32
#define CIN 64
#define H 128
#define W 128
#define OC 64
#define OH 64
#define OW 64

__device__ unsigned int g_xlo[NB * H * W];   // 2 MB: channels 0-31 sign bits
__device__ unsigned int g_xhi[NB * H * W];   // 2 MB: channels 32-63 sign bits
// B fragments: [(tap*8 + j)*32 + lane] -> uint4 (b0_k0, b1_k0, b0_k1, b1_k1)
// for n-cols (o) 8j..8j+7; lane = gq*4+qc, o = 8j+gq, k-cols 4qc..4qc+3 (+16).
__device__ uint4 g_wfrag[9 * 8 * 32];

// ---------------------------------------------------------------------------
// nibble (4 sign bits) -> 4 packed s8: bit=1 -> +1 (0x01), bit=0 -> -1 (0xFF)
// ---------------------------------------------------------------------------
__device__ __forceinline__ unsigned int expand4(unsigned int nib) {
    unsigned int s = (nib | (nib << 7) | (nib << 14) | (nib << 21)) & 0x01010101u;
    return (s * 0xFEu) ^ 0xFFFFFFFFu;
}

__device__ __forceinline__ void mma_s8(int* c,
    unsigned int a0, unsigned int a1, unsigned int a2, unsigned int a3,
    unsigned int b0, unsigned int b1) {
    asm volatile(
        "mma.sync.aligned.m16n8k32.row.col.s32.s8.s8.s32 "
        "{%0,%1,%2,%3}, {%4,%5,%6,%7}, {%8,%9}, {%0,%1,%2,%3};"
        : "+r"(c[0]), "+r"(c[1]), "+r"(c[2]), "+r"(c[3])
        : "r"(a0), "r"(a1), "r"(a2), "r"(a3), "r"(b0), "r"(b1));
}

// ---------------------------------------------------------------------------
// Pack x (proven: ~24us, ~70% DRAM)
// ---------------------------------------------------------------------------
__global__ void __launch_bounds__(256) pack_x_kernel(const float* __restrict__ x) {
    int g = blockIdx.x * blockDim.x + threadIdx.x;
    int half = g & 1;
    int w4   = ((g >> 1) & 31) * 4;
    int h    = (g >> 6) & 127;
    int n    = g >> 13;

    const float* base = x + ((long)(n * CIN + half * 32) * H + h) * W + w4;

    unsigned int b0 = 0, b1 = 0, b2 = 0, b3 = 0;
#pragma unroll 16
    for (int c = 0; c < 32; c++) {
        float4 v = *reinterpret_cast<const float4*>(base + (long)c * (H * W));
        b0 |= (unsigned int)(v.x >= 0.0f) << c;
        b1 |= (unsigned int)(v.y >= 0.0f) << c;
        b2 |= (unsigned int)(v.z >= 0.0f) << c;
        b3 |= (unsigned int)(v.w >= 0.0f) << c;
    }
    unsigned int* plane = half ? g_xhi : g_xlo;
    uint4 val; val.x = b0; val.y = b1; val.z = b2; val.w = b3;
    *reinterpret_cast<uint4*>(plane + ((long)(n * H + h) * W + w4)) = val;
}

// ---------------------------------------------------------------------------
// Pack w (parallel): one CTA per output channel o, 64 threads = input channels.
// Thread i reads its 9 contiguous taps (warp = 1152B coalesced), ballot packs
// per-tap sign masks, then threads 0..35 emit this o's 36 B-fragments.
// Fragment math identical to R9 (verified rel_err 0).
// ---------------------------------------------------------------------------
__global__ void __launch_bounds__(64) pack_w_kernel(const float* __restrict__ w) {
    __shared__ unsigned int s_lo[9], s_hi[9];
    int o    = blockIdx.x;
    int i    = threadIdx.x;          // input channel
    int warp = i >> 5;
    int lane = i & 31;

    const float* wr = w + (o * CIN + i) * 9;
    float v[9];
#pragma unroll
    for (int t = 0; t < 9; t++) v[t] = wr[t];

#pragma unroll
    for (int t = 0; t < 9; t++) {
        unsigned int m = __ballot_sync(0xFFFFFFFFu, v[t] >= 0.0f);
        if (lane == 0) { if (warp == 0) s_lo[t] = m; else s_hi[t] = m; }
    }
    __syncthreads();

    if (i < 36) {
        int tap = i >> 2;            // 0..8
        int qc  = i & 3;             // k quad
        unsigned long long wb =
            (unsigned long long)s_lo[tap] | ((unsigned long long)s_hi[tap] << 32);
        uint4 f;
        f.x = expand4((unsigned int)(wb >> (4 * qc))      & 0xFu);  // k0, b0
        f.y = expand4((unsigned int)(wb >> (16 + 4 * qc)) & 0xFu);  // k0, b1
        f.z = expand4((unsigned int)(wb >> (32 + 4 * qc)) & 0xFu);  // k1, b0
        f.w = expand4((unsigned int)(wb >> (48 + 4 * qc)) & 0xFu);  // k1, b1
        g_wfrag[(tap * 8 + (o >> 3)) * 32 + (o & 7) * 4 + qc] = f;
    }
}

// ---------------------------------------------------------------------------
// Conv (unchanged from R9, verified): warp = 16 ow x N=64 oc, K=576 as
// 18 k32 IMMA steps; pad rows expand to s8 zeros (contribute 0).
// 8192 warps = 1024 CTAs x 256 thr.
// ---------------------------------------------------------------------------
__global__ void __launch_bounds__(256) conv_mma_kernel(float* __restrict__ out) {
    int gw   = (blockIdx.x * 256 + threadIdx.x) >> 5;   // 0..8191
    int lane = threadIdx.x & 31;
    int ow0  = (gw & 3) * 16;
    int oh   = (gw >> 2) & 63;
    int n    = gw >> 8;
    int qr   = lane >> 2;      // row in group (0..7)
    int qc   = lane & 3;
    int ow_a = ow0 + qr;
    int ow_b = ow_a + 8;

    const unsigned int* xl = g_xlo + (long)n * (H * W);
    const unsigned int* xh = g_xhi + (long)n * (H * W);

    int acc[32];
#pragma unroll
    for (int i = 0; i < 32; i++) acc[i] = 0;

    int sh0 = 4 * qc;
    int sh1 = 16 + 4 * qc;

#pragma unroll
    for (int kh = 0; kh < 3; kh++) {
        int ih = 2 * oh - 1 + kh;
        bool vr = (ih >= 0);                 // ih <= 127 always
#pragma unroll
        for (int kw = 0; kw < 3; kw++) {
            int tap = kh * 3 + kw;
            int iwa = 2 * ow_a - 1 + kw;     // [-1, 127]
            int iwb = iwa + 16;              // always >= 15
            bool pa = vr && (iwa >= 0);
            bool pb = vr;

            unsigned int loa = pa ? xl[ih * W + iwa] : 0u;
            unsigned int hia = pa ? xh[ih * W + iwa] : 0u;
            unsigned int lob = pb ? xl[ih * W + iwb] : 0u;
            unsigned int hib = pb ? xh[ih * W + iwb] : 0u;

            unsigned int a0 = pa ? expand4((loa >> sh0) & 0xFu) : 0u;
            unsigned int a1 = pb ? expand4((lob >> sh0) & 0xFu) : 0u;
            unsigned int a2 = pa ? expand4((loa >> sh1) & 0xFu) : 0u;
            unsigned int a3 = pb ? expand4((lob >> sh1) & 0xFu) : 0u;
            unsigned int a4 = pa ? expand4((hia >> sh0) & 0xFu) : 0u;
            unsigned int a5 = pb ? expand4((hib >> sh0) & 0xFu) : 0u;
            unsigned int a6 = pa ? expand4((hia >> sh1) & 0xFu) : 0u;
            unsigned int a7 = pb ? expand4((hib >> sh1) & 0xFu) : 0u;

            const uint4* wf = g_wfrag + tap * 8 * 32 + lane;
#pragma unroll
            for (int j = 0; j < 8; j++) {
                uint4 b = wf[j * 32];
                mma_s8(acc + 4 * j, a0, a1, a2, a3, b.x, b.y);  // channels 0-31
                mma_s8(acc + 4 * j, a4, a5, a6, a7, b.z, b.w);  // channels 32-63
            }
        }
    }

    float* ob = out + ((long)(n * OC) * OH + oh) * OW;
#pragma unroll
    for (int j = 0; j < 8; j++) {
        int o0 = 8 * j + 2 * qc;
        float* p0 = ob + (long)o0 * (OH * OW);
        float* p1 = p0 + (OH * OW);
        p0[ow_a] = (float)acc[4 * j + 0];
        p1[ow_a] = (float)acc[4 * j + 1];
        p0[ow_b] = (float)acc[4 * j + 2];
        p1[ow_b] = (float)acc[4 * j + 3];
    }
}

// ---------------------------------------------------------------------------
extern "C" void kernel_launch(void* const* d_in, const int* in_sizes, int n_in,
                              void* d_out, int out_size) {
    const float* x = (const float*)d_in[0];
    const float* w = (const float*)d_in[1];
    float* out = (float*)d_out;

    pack_x_kernel<<<1024, 256>>>(x);
    pack_w_kernel<<<64, 64>>>(w);
    conv_mma_kernel<<<1024, 256>>>(out);
}